// round 1
// baseline (speedup 1.0000x reference)
#include <cuda_runtime.h>
#include <cuda_bf16.h>
#include <math.h>

// Problem dims
#define BDIM 8
#define SDIM 4096
#define EDIM 256
#define HDIM 4
#define DK   64
#define MTOT (BDIM * SDIM)   // 32768 tokens

// GEMM tiling
#define BM 64
#define BN 64
#define BK 32
#define TM 4
#define TN 4
#define NTHREADS 256

// Scratch (device globals — no runtime allocation allowed)
__device__ float g_q[(size_t)MTOT * EDIM];
__device__ float g_k[(size_t)MTOT * EDIM];
__device__ float g_v[(size_t)MTOT * EDIM];
__device__ float g_y[(size_t)MTOT * EDIM];

// C[M,N] = A[M,K] @ W[N,K]^T + bias[N]   (torch Linear convention)
__global__ __launch_bounds__(NTHREADS)
void gemm_nt_kernel(const float* __restrict__ A,
                    const float* __restrict__ W,
                    const float* __restrict__ bias,
                    float* __restrict__ C,
                    int M, int N, int K)
{
    __shared__ float As[BK][BM + 1];
    __shared__ float Bs[BK][BN + 1];

    const int tid = threadIdx.x;
    const int m0 = blockIdx.y * BM;
    const int n0 = blockIdx.x * BN;

    const int tx = tid % (BN / TN);   // 0..15 -> n
    const int ty = tid / (BN / TN);   // 0..15 -> m
    const int lk = tid & 31;          // k within tile
    const int lr = tid >> 5;          // 0..7 row group

    float acc[TM][TN];
#pragma unroll
    for (int i = 0; i < TM; i++)
#pragma unroll
        for (int j = 0; j < TN; j++) acc[i][j] = 0.0f;

    for (int k0 = 0; k0 < K; k0 += BK) {
#pragma unroll
        for (int r = 0; r < BM; r += 8)
            As[lk][r + lr] = A[(size_t)(m0 + r + lr) * K + k0 + lk];
#pragma unroll
        for (int r = 0; r < BN; r += 8)
            Bs[lk][r + lr] = W[(size_t)(n0 + r + lr) * K + k0 + lk];
        __syncthreads();

#pragma unroll
        for (int k = 0; k < BK; k++) {
            float a[TM], b[TN];
#pragma unroll
            for (int i = 0; i < TM; i++) a[i] = As[k][ty * TM + i];
#pragma unroll
            for (int j = 0; j < TN; j++) b[j] = Bs[k][tx * TN + j];
#pragma unroll
            for (int i = 0; i < TM; i++)
#pragma unroll
                for (int j = 0; j < TN; j++) acc[i][j] = fmaf(a[i], b[j], acc[i][j]);
        }
        __syncthreads();
    }

#pragma unroll
    for (int i = 0; i < TM; i++) {
        const size_t row = (size_t)(m0 + ty * TM + i) * N;
#pragma unroll
        for (int j = 0; j < TN; j++) {
            const int n = n0 + tx * TN + j;
            C[row + n] = acc[i][j] + bias[n];
        }
    }
}

// Per-token attention over HEADS: q,k,v are [MTOT][H*DK] per token.
// scores[h][g] = dot(q[h,:], k[g,:]) / sqrt(DK); softmax over g; y[h,:] = p @ v.
// One warp per token; lanes split the DK=64 dim (2 elems per lane).
__global__ __launch_bounds__(256)
void attn_heads_kernel(const float* __restrict__ q,
                       const float* __restrict__ k,
                       const float* __restrict__ v,
                       float* __restrict__ y)
{
    const int t = blockIdx.x * 8 + (threadIdx.x >> 5);
    const int lane = threadIdx.x & 31;
    if (t >= MTOT) return;

    const float* qt = q + (size_t)t * EDIM;
    const float* kt = k + (size_t)t * EDIM;
    const float* vt = v + (size_t)t * EDIM;
    float* yt = y + (size_t)t * EDIM;

    float qv[HDIM][2], kv[HDIM][2], vv[HDIM][2];
#pragma unroll
    for (int h = 0; h < HDIM; h++)
#pragma unroll
        for (int j = 0; j < 2; j++) {
            const int idx = h * DK + j * 32 + lane;
            qv[h][j] = qt[idx];
            kv[h][j] = kt[idx];
            vv[h][j] = vt[idx];
        }

    float s[HDIM][HDIM];
#pragma unroll
    for (int h = 0; h < HDIM; h++)
#pragma unroll
        for (int g = 0; g < HDIM; g++) {
            float p = qv[h][0] * kv[g][0] + qv[h][1] * kv[g][1];
#pragma unroll
            for (int off = 16; off > 0; off >>= 1)
                p += __shfl_xor_sync(0xFFFFFFFFu, p, off);
            s[h][g] = p * 0.125f;   // 1/sqrt(64)
        }

    // softmax over g (every lane holds the full 4x4 score matrix)
    float p[HDIM][HDIM];
#pragma unroll
    for (int h = 0; h < HDIM; h++) {
        float m = s[h][0];
#pragma unroll
        for (int g = 1; g < HDIM; g++) m = fmaxf(m, s[h][g]);
        float sum = 0.0f;
#pragma unroll
        for (int g = 0; g < HDIM; g++) { p[h][g] = __expf(s[h][g] - m); sum += p[h][g]; }
        const float inv = 1.0f / sum;
#pragma unroll
        for (int g = 0; g < HDIM; g++) p[h][g] *= inv;
    }

#pragma unroll
    for (int h = 0; h < HDIM; h++)
#pragma unroll
        for (int j = 0; j < 2; j++) {
            float acc = 0.0f;
#pragma unroll
            for (int g = 0; g < HDIM; g++) acc = fmaf(p[h][g], vv[g][j], acc);
            yt[h * DK + j * 32 + lane] = acc;
        }
}

extern "C" void kernel_launch(void* const* d_in, const int* in_sizes, int n_in,
                              void* d_out, int out_size)
{
    const float* x  = (const float*)d_in[0];
    const float* Wq = (const float*)d_in[1];
    const float* bq = (const float*)d_in[2];
    const float* Wk = (const float*)d_in[3];
    const float* bk = (const float*)d_in[4];
    const float* Wv = (const float*)d_in[5];
    const float* bv = (const float*)d_in[6];
    const float* Wo = (const float*)d_in[7];
    const float* bo = (const float*)d_in[8];
    float* out = (float*)d_out;

    float *q, *k, *v, *y;
    cudaGetSymbolAddress((void**)&q, g_q);
    cudaGetSymbolAddress((void**)&k, g_k);
    cudaGetSymbolAddress((void**)&v, g_v);
    cudaGetSymbolAddress((void**)&y, g_y);

    dim3 grid(EDIM / BN, MTOT / BM);

    gemm_nt_kernel<<<grid, NTHREADS>>>(x, Wq, bq, q, MTOT, EDIM, EDIM);
    gemm_nt_kernel<<<grid, NTHREADS>>>(x, Wk, bk, k, MTOT, EDIM, EDIM);
    gemm_nt_kernel<<<grid, NTHREADS>>>(x, Wv, bv, v, MTOT, EDIM, EDIM);

    attn_heads_kernel<<<MTOT / 8, 256>>>(q, k, v, y);

    gemm_nt_kernel<<<grid, NTHREADS>>>(y, Wo, bo, out, MTOT, EDIM, EDIM);
}

// round 3
// speedup vs baseline: 2.8010x; 2.8010x over previous
#include <cuda_runtime.h>
#include <cuda_fp16.h>
#include <cuda_bf16.h>
#include <cstdint>

#define BDIM 8
#define SDIM 4096
#define EDIM 256
#define HDIM 4
#define DK   64
#define MTOT (BDIM * SDIM)   // 32768

// ---------------- scratch (device globals; no runtime alloc) -------------------
__device__ __half g_xh[(size_t)MTOT * EDIM];
__device__ __half g_xl[(size_t)MTOT * EDIM];
__device__ __half g_yh[(size_t)MTOT * EDIM];
__device__ __half g_yl[(size_t)MTOT * EDIM];
__device__ float  g_q[(size_t)MTOT * EDIM];
__device__ float  g_k[(size_t)MTOT * EDIM];
__device__ float  g_v[(size_t)MTOT * EDIM];
__device__ __half g_wh[4][EDIM * EDIM];
__device__ __half g_wl[4][EDIM * EDIM];

// ---------------- helpers ------------------------------------------------------
__device__ __forceinline__ uint32_t smem_u32(const void* p) {
    uint32_t a;
    asm("{ .reg .u64 t; cvta.to.shared.u64 t, %1; cvt.u32.u64 %0, t; }" : "=r"(a) : "l"(p));
    return a;
}

#define CP_ASYNC16(smem, gmem) \
    asm volatile("cp.async.cg.shared.global [%0], [%1], 16;" :: "r"(smem), "l"(gmem))
#define CP_ASYNC_COMMIT() asm volatile("cp.async.commit_group;")
#define CP_ASYNC_WAIT0()  asm volatile("cp.async.wait_group 0;")

#define LDMATRIX_X4(r0, r1, r2, r3, addr) \
    asm volatile("ldmatrix.sync.aligned.m8n8.x4.shared.b16 {%0,%1,%2,%3}, [%4];" \
        : "=r"(r0), "=r"(r1), "=r"(r2), "=r"(r3) : "r"(addr))

#define MMA16816(c, a, b0, b1) \
    asm volatile("mma.sync.aligned.m16n8k16.row.col.f32.f16.f16.f32 " \
        "{%0,%1,%2,%3}, {%4,%5,%6,%7}, {%8,%9}, {%0,%1,%2,%3};" \
        : "+f"((c)[0]), "+f"((c)[1]), "+f"((c)[2]), "+f"((c)[3]) \
        : "r"((a)[0]), "r"((a)[1]), "r"((a)[2]), "r"((a)[3]), "r"(b0), "r"(b1))

// ---------------- split: fp32 -> fp16 hi + fp16 lo ------------------------------
__global__ void split_kernel(const float4* __restrict__ src,
                             uint2* __restrict__ hi, uint2* __restrict__ lo, int n4)
{
    int i = blockIdx.x * blockDim.x + threadIdx.x;
    if (i >= n4) return;
    float4 v = src[i];
    __half h0 = __float2half_rn(v.x), h1 = __float2half_rn(v.y);
    __half h2 = __float2half_rn(v.z), h3 = __float2half_rn(v.w);
    __half2 ph0{h0, h1}, ph1{h2, h3};
    __half2 pl0{__float2half_rn(v.x - __half2float(h0)),
                __float2half_rn(v.y - __half2float(h1))};
    __half2 pl1{__float2half_rn(v.z - __half2float(h2)),
                __float2half_rn(v.w - __half2float(h3))};
    uint2 H, L;
    H.x = *(uint32_t*)&ph0; H.y = *(uint32_t*)&ph1;
    L.x = *(uint32_t*)&pl0; L.y = *(uint32_t*)&pl1;
    hi[i] = H; lo[i] = L;
}

// ---------------- HMMA GEMM: C[M,256] = (Ah+Al)(Wh+Wl)^T + bias -----------------
// CTA tile 128x128, BK=64, 8 warps in 4(m) x 2(n), warp tile 32x64.
#define BM 128
#define BN 128
#define BK 64
#define GT 256
#define LDT 72                      // padded row stride in halves (16B aligned)
#define TILE_HALFS (BM * LDT)       // 9216

__global__ __launch_bounds__(GT, 2)
void hmma_gemm_kernel(const __half* __restrict__ Ah,
                      const __half* __restrict__ Al,
                      const __half* __restrict__ Wh,
                      const __half* __restrict__ Wl,
                      const float* __restrict__ bias,
                      float* __restrict__ C)
{
    extern __shared__ __half smem[];
    __half* sAh = smem;
    __half* sAl = smem + TILE_HALFS;
    __half* sWh = smem + 2 * TILE_HALFS;
    __half* sWl = smem + 3 * TILE_HALFS;

    const int tid = threadIdx.x;
    const int wid = tid >> 5;
    const int lane = tid & 31;
    const int m0 = blockIdx.y * BM;
    const int n0 = blockIdx.x * BN;
    const int warp_m = (wid & 3) * 32;
    const int warp_n = (wid >> 2) * 64;

    const uint32_t sAh_b = smem_u32(sAh);
    const uint32_t sAl_b = smem_u32(sAl);
    const uint32_t sWh_b = smem_u32(sWh);
    const uint32_t sWl_b = smem_u32(sWl);

    float acc[2][8][4];
#pragma unroll
    for (int i = 0; i < 2; i++)
#pragma unroll
        for (int j = 0; j < 8; j++)
#pragma unroll
            for (int r = 0; r < 4; r++) acc[i][j][r] = 0.0f;

    for (int k0 = 0; k0 < EDIM; k0 += BK) {
        // load 4 tiles of [128 rows x 64 halves] via cp.async (16B chunks)
#pragma unroll
        for (int i = 0; i < 4; i++) {
            const int c = tid + i * GT;         // 0..1023
            const int row = c >> 3;
            const int kc = (c & 7) << 3;        // half offset within row
            const uint32_t soff = (uint32_t)(row * LDT + kc) * 2;
            const size_t aoff = (size_t)(m0 + row) * EDIM + k0 + kc;
            const size_t woff = (size_t)(n0 + row) * EDIM + k0 + kc;
            CP_ASYNC16(sAh_b + soff, Ah + aoff);
            CP_ASYNC16(sAl_b + soff, Al + aoff);
            CP_ASYNC16(sWh_b + soff, Wh + woff);
            CP_ASYNC16(sWl_b + soff, Wl + woff);
        }
        CP_ASYNC_COMMIT();
        CP_ASYNC_WAIT0();
        __syncthreads();

#pragma unroll
        for (int ks = 0; ks < BK / 16; ks++) {
            const int k = ks * 16;
            // A fragments (hi & lo)
            uint32_t ah[2][4], al[2][4];
#pragma unroll
            for (int mf = 0; mf < 2; mf++) {
                const uint32_t off =
                    (uint32_t)((warp_m + mf * 16 + (lane & 15)) * LDT + k + ((lane >> 4) << 3)) * 2;
                LDMATRIX_X4(ah[mf][0], ah[mf][1], ah[mf][2], ah[mf][3], sAh_b + off);
                LDMATRIX_X4(al[mf][0], al[mf][1], al[mf][2], al[mf][3], sAl_b + off);
            }
            // B fragments in pairs of n-frags
#pragma unroll
            for (int np = 0; np < 4; np++) {
                const uint32_t boff =
                    (uint32_t)((warp_n + np * 16 + (lane & 7) + ((lane >> 4) << 3)) * LDT
                               + k + (((lane >> 3) & 1) << 3)) * 2;
                uint32_t bh[4], bl[4];
                LDMATRIX_X4(bh[0], bh[1], bh[2], bh[3], sWh_b + boff);
                LDMATRIX_X4(bl[0], bl[1], bl[2], bl[3], sWl_b + boff);
#pragma unroll
                for (int mf = 0; mf < 2; mf++) {
                    MMA16816(acc[mf][np * 2],     ah[mf], bh[0], bh[1]);
                    MMA16816(acc[mf][np * 2],     ah[mf], bl[0], bl[1]);
                    MMA16816(acc[mf][np * 2],     al[mf], bh[0], bh[1]);
                    MMA16816(acc[mf][np * 2 + 1], ah[mf], bh[2], bh[3]);
                    MMA16816(acc[mf][np * 2 + 1], ah[mf], bl[2], bl[3]);
                    MMA16816(acc[mf][np * 2 + 1], al[mf], bh[2], bh[3]);
                }
            }
        }
        __syncthreads();
    }

    // epilogue: C = acc + bias
#pragma unroll
    for (int mf = 0; mf < 2; mf++) {
        const int r0 = m0 + warp_m + mf * 16 + (lane >> 2);
#pragma unroll
        for (int nf = 0; nf < 8; nf++) {
            const int col = n0 + warp_n + nf * 8 + (lane & 3) * 2;
            const float b0 = bias[col], b1 = bias[col + 1];
            float2 v0{acc[mf][nf][0] + b0, acc[mf][nf][1] + b1};
            float2 v1{acc[mf][nf][2] + b0, acc[mf][nf][3] + b1};
            *(float2*)(C + (size_t)r0 * EDIM + col) = v0;
            *(float2*)(C + (size_t)(r0 + 8) * EDIM + col) = v1;
        }
    }
}

// ---------------- attention over heads; fused y -> (yh, yl) fp16 split ----------
__global__ __launch_bounds__(256)
void attn_heads_kernel(const float* __restrict__ q,
                       const float* __restrict__ k,
                       const float* __restrict__ v,
                       __half* __restrict__ yh,
                       __half* __restrict__ yl)
{
    const int t = blockIdx.x * 8 + (threadIdx.x >> 5);
    const int lane = threadIdx.x & 31;
    if (t >= MTOT) return;

    const float* qt = q + (size_t)t * EDIM;
    const float* kt = k + (size_t)t * EDIM;
    const float* vt = v + (size_t)t * EDIM;

    float qv[HDIM][2], kv[HDIM][2], vv[HDIM][2];
#pragma unroll
    for (int h = 0; h < HDIM; h++)
#pragma unroll
        for (int j = 0; j < 2; j++) {
            const int idx = h * DK + j * 32 + lane;
            qv[h][j] = qt[idx];
            kv[h][j] = kt[idx];
            vv[h][j] = vt[idx];
        }

    float s[HDIM][HDIM];
#pragma unroll
    for (int h = 0; h < HDIM; h++)
#pragma unroll
        for (int g = 0; g < HDIM; g++) {
            float p = qv[h][0] * kv[g][0] + qv[h][1] * kv[g][1];
#pragma unroll
            for (int off = 16; off > 0; off >>= 1)
                p += __shfl_xor_sync(0xFFFFFFFFu, p, off);
            s[h][g] = p * 0.125f;
        }

    float p[HDIM][HDIM];
#pragma unroll
    for (int h = 0; h < HDIM; h++) {
        float m = s[h][0];
#pragma unroll
        for (int g = 1; g < HDIM; g++) m = fmaxf(m, s[h][g]);
        float sum = 0.0f;
#pragma unroll
        for (int g = 0; g < HDIM; g++) { p[h][g] = __expf(s[h][g] - m); sum += p[h][g]; }
        const float inv = 1.0f / sum;
#pragma unroll
        for (int g = 0; g < HDIM; g++) p[h][g] *= inv;
    }

#pragma unroll
    for (int h = 0; h < HDIM; h++)
#pragma unroll
        for (int j = 0; j < 2; j++) {
            float acc = 0.0f;
#pragma unroll
            for (int g = 0; g < HDIM; g++) acc = fmaf(p[h][g], vv[g][j], acc);
            const int idx = h * DK + j * 32 + lane;
            __half hh = __float2half_rn(acc);
            yh[(size_t)t * EDIM + idx] = hh;
            yl[(size_t)t * EDIM + idx] = __float2half_rn(acc - __half2float(hh));
        }
}

// ---------------- launch --------------------------------------------------------
extern "C" void kernel_launch(void* const* d_in, const int* in_sizes, int n_in,
                              void* d_out, int out_size)
{
    const float* x  = (const float*)d_in[0];
    const float* Wq = (const float*)d_in[1];
    const float* bq = (const float*)d_in[2];
    const float* Wk = (const float*)d_in[3];
    const float* bk = (const float*)d_in[4];
    const float* Wv = (const float*)d_in[5];
    const float* bv = (const float*)d_in[6];
    const float* Wo = (const float*)d_in[7];
    const float* bo = (const float*)d_in[8];
    float* out = (float*)d_out;

    __half *xh, *xl, *yh, *yl;
    float *q, *k, *v;
    __half (*wh)[EDIM * EDIM], (*wl)[EDIM * EDIM];
    cudaGetSymbolAddress((void**)&xh, g_xh);
    cudaGetSymbolAddress((void**)&xl, g_xl);
    cudaGetSymbolAddress((void**)&yh, g_yh);
    cudaGetSymbolAddress((void**)&yl, g_yl);
    cudaGetSymbolAddress((void**)&q, g_q);
    cudaGetSymbolAddress((void**)&k, g_k);
    cudaGetSymbolAddress((void**)&v, g_v);
    cudaGetSymbolAddress((void**)&wh, g_wh);
    cudaGetSymbolAddress((void**)&wl, g_wl);

    const int smem_bytes = 4 * TILE_HALFS * 2;   // 73728
    cudaFuncSetAttribute(hmma_gemm_kernel,
                         cudaFuncAttributeMaxDynamicSharedMemorySize, smem_bytes);

    // split inputs into fp16 hi/lo
    {
        int n4 = MTOT * EDIM / 4;
        split_kernel<<<n4 / 256, 256>>>((const float4*)x, (uint2*)xh, (uint2*)xl, n4);
        int w4 = EDIM * EDIM / 4;
        split_kernel<<<w4 / 256, 256>>>((const float4*)Wq, (uint2*)wh[0], (uint2*)wl[0], w4);
        split_kernel<<<w4 / 256, 256>>>((const float4*)Wk, (uint2*)wh[1], (uint2*)wl[1], w4);
        split_kernel<<<w4 / 256, 256>>>((const float4*)Wv, (uint2*)wh[2], (uint2*)wl[2], w4);
        split_kernel<<<w4 / 256, 256>>>((const float4*)Wo, (uint2*)wh[3], (uint2*)wl[3], w4);
    }

    dim3 ggrid(EDIM / BN, MTOT / BM);   // (2, 256)

    hmma_gemm_kernel<<<ggrid, GT, smem_bytes>>>(xh, xl, wh[0], wl[0], bq, q);
    hmma_gemm_kernel<<<ggrid, GT, smem_bytes>>>(xh, xl, wh[1], wl[1], bk, k);
    hmma_gemm_kernel<<<ggrid, GT, smem_bytes>>>(xh, xl, wh[2], wl[2], bv, v);

    attn_heads_kernel<<<MTOT / 8, 256>>>(q, k, v, yh, yl);

    hmma_gemm_kernel<<<ggrid, GT, smem_bytes>>>(yh, yl, wh[3], wl[3], bo, out);
}